// round 1
// baseline (speedup 1.0000x reference)
#include <cuda_runtime.h>
#include <math.h>

#define VOCAB 32000
#define EMB 128
#define HID 128
#define NLAB 9
#define BATCH 128
#define SEQ 1024
#define NTOK (BATCH * SEQ)

// Scratch (static device arrays: allocation-free, overwrite-only => graph-replay safe)
__device__ float g_T[VOCAB * HID];              // emb_table @ Wx + b_h   (16.4 MB, L2-resident)
__device__ float g_hidden[(size_t)NTOK * HID];  // hidden states (64 MB)
__device__ float g_partial[512];                // per-CTA loss partials

// ---------------------------------------------------------------------------
// Kernel 1: T[v][j] = sum_e emb[v][e] * W_h[e][j] + b_h[j]
// Thread j holds Wx[:,j] in registers; embedding rows staged in double-buffered SMEM.
// ---------------------------------------------------------------------------
__global__ void __launch_bounds__(128) k_precompute(const float* __restrict__ emb,
                                                    const float* __restrict__ W_h,
                                                    const float* __restrict__ b_h) {
    const int j = threadIdx.x;
    float wx[EMB];
#pragma unroll
    for (int e = 0; e < EMB; e++) wx[e] = W_h[e * HID + j];
    const float bj = b_h[j];

    __shared__ float es[2][EMB];
    const int row0 = blockIdx.x * 128;

    es[0][j] = emb[(size_t)row0 * EMB + j];
    __syncthreads();

    for (int r = 0; r < 128; r++) {
        const int buf = r & 1;
        const int row = row0 + r;
        if (r + 1 < 128) es[buf ^ 1][j] = emb[(size_t)(row + 1) * EMB + j];

        float a0 = bj, a1 = 0.f, a2 = 0.f, a3 = 0.f;
        const float4* e4 = (const float4*)es[buf];
#pragma unroll
        for (int k = 0; k < EMB / 4; k++) {
            float4 v = e4[k];
            a0 += v.x * wx[4 * k + 0];
            a1 += v.y * wx[4 * k + 1];
            a2 += v.z * wx[4 * k + 2];
            a3 += v.w * wx[4 * k + 3];
        }
        g_T[row * HID + j] = (a0 + a1) + (a2 + a3);
        __syncthreads();
    }
}

// ---------------------------------------------------------------------------
// Kernel 2: sequential scan. One CTA per batch row, 128 threads (thread j = column j).
// Wh[:,j] register-resident; h double-buffered in SMEM; xw gathered from g_T with
// one-step prefetch; one barrier per step.
// ---------------------------------------------------------------------------
__global__ void __launch_bounds__(128) k_scan(const int* __restrict__ ids,
                                              const float* __restrict__ W_h) {
    const int b = blockIdx.x;
    const int j = threadIdx.x;

    float wh[HID];
#pragma unroll
    for (int k = 0; k < HID; k++) wh[k] = W_h[(EMB + k) * HID + j];

    __shared__ float hs[2][HID];
    __shared__ int ids_sh[SEQ];
    const int* idrow = ids + b * SEQ;
#pragma unroll
    for (int t = j; t < SEQ; t += 128) ids_sh[t] = idrow[t];
    hs[0][j] = 0.f;
    __syncthreads();

    float* hout = g_hidden + (size_t)b * SEQ * HID;
    float xw = g_T[ids_sh[0] * HID + j];

    for (int t = 0; t < SEQ; t++) {
        const int idn = ids_sh[(t + 1 < SEQ) ? (t + 1) : t];
        const float xw_next = g_T[idn * HID + j];  // prefetch next step (L2 hit ~234cyc, hidden)

        const int buf = t & 1;
        const float4* h4 = (const float4*)hs[buf];
        float a0 = xw, a1 = 0.f, a2 = 0.f, a3 = 0.f;
#pragma unroll
        for (int k = 0; k < HID / 4; k++) {
            float4 v = h4[k];
            a0 += v.x * wh[4 * k + 0];
            a1 += v.y * wh[4 * k + 1];
            a2 += v.z * wh[4 * k + 2];
            a3 += v.w * wh[4 * k + 3];
        }
        const float hv = tanhf((a0 + a1) + (a2 + a3));
        hs[buf ^ 1][j] = hv;
        hout[(size_t)t * HID + j] = hv;
        xw = xw_next;
        __syncthreads();
    }
}

// ---------------------------------------------------------------------------
// Kernel 3: logits + per-token NLL. One warp per token (strided).
// Butterfly-reduce the 9 dot products; lanes 0..8 write logits; lane 0 does loss.
// Per-CTA partials are OVERWRITTEN (deterministic, replay-safe).
// ---------------------------------------------------------------------------
__global__ void __launch_bounds__(256) k_logits(const int* __restrict__ labels,
                                                const float* __restrict__ W_out,
                                                const float* __restrict__ b_out,
                                                float* __restrict__ out_logits) {
    __shared__ float Wsh[HID * NLAB];
    __shared__ float bsh[NLAB];
    __shared__ float wsum[8];
    const int tid = threadIdx.x;
    for (int i = tid; i < HID * NLAB; i += blockDim.x) Wsh[i] = W_out[i];
    if (tid < NLAB) bsh[tid] = b_out[tid];
    __syncthreads();

    const int lane = tid & 31, warp = tid >> 5;
    const int gwarp = blockIdx.x * (blockDim.x >> 5) + warp;
    const int nwarp = gridDim.x * (blockDim.x >> 5);
    float lsum = 0.f;

    for (int tok = gwarp; tok < NTOK; tok += nwarp) {
        const float* h = g_hidden + (size_t)tok * HID;
        const float h0 = h[lane], h1 = h[lane + 32], h2 = h[lane + 64], h3 = h[lane + 96];
        float lg[NLAB];
#pragma unroll
        for (int l = 0; l < NLAB; l++) {
            float p = h0 * Wsh[lane * NLAB + l]
                    + h1 * Wsh[(lane + 32) * NLAB + l]
                    + h2 * Wsh[(lane + 64) * NLAB + l]
                    + h3 * Wsh[(lane + 96) * NLAB + l];
#pragma unroll
            for (int off = 16; off; off >>= 1) p += __shfl_xor_sync(0xffffffffu, p, off);
            lg[l] = p + bsh[l];
        }
        if (lane < NLAB) out_logits[(size_t)tok * NLAB + lane] = lg[lane];
        if (lane == 0) {
            float m = lg[0];
#pragma unroll
            for (int l = 1; l < NLAB; l++) m = fmaxf(m, lg[l]);
            float s = 0.f;
#pragma unroll
            for (int l = 0; l < NLAB; l++) s += expf(lg[l] - m);
            const float lse = m + logf(s);
            lsum += lse - lg[labels[tok]];
        }
    }
    if (lane == 0) wsum[warp] = lsum;
    __syncthreads();
    if (tid == 0) {
        float s = 0.f;
#pragma unroll
        for (int w = 0; w < 8; w++) s += wsum[w];
        g_partial[blockIdx.x] = s;  // overwrite, no accumulation across replays
    }
}

// ---------------------------------------------------------------------------
// Kernel 4: reduce partials -> loss scalar
// ---------------------------------------------------------------------------
__global__ void __launch_bounds__(256) k_loss(float* __restrict__ out_loss, int nblocks) {
    __shared__ float s[256];
    float v = 0.f;
    for (int i = threadIdx.x; i < nblocks; i += 256) v += g_partial[i];
    s[threadIdx.x] = v;
    __syncthreads();
    for (int st = 128; st; st >>= 1) {
        if (threadIdx.x < st) s[threadIdx.x] += s[threadIdx.x + st];
        __syncthreads();
    }
    if (threadIdx.x == 0) out_loss[0] = s[0] / (float)NTOK;
}

// ---------------------------------------------------------------------------
// Inputs (metadata order): 0 input_ids(i32), 1 attention_mask(i32, unused),
// 2 token_type_ids(i32, unused), 3 labels(i32), 4 emb_table(f32),
// 5 W_h(f32 256x128), 6 b_h(f32), 7 W_out(f32 128x9), 8 b_out(f32)
// Output: logits (B*S*9 f32) followed by loss scalar at out_size-1.
// ---------------------------------------------------------------------------
extern "C" void kernel_launch(void* const* d_in, const int* in_sizes, int n_in,
                              void* d_out, int out_size) {
    const int*   input_ids = (const int*)d_in[0];
    const int*   labels    = (const int*)d_in[3];
    const float* emb_table = (const float*)d_in[4];
    const float* W_h       = (const float*)d_in[5];
    const float* b_h       = (const float*)d_in[6];
    const float* W_out     = (const float*)d_in[7];
    const float* b_out     = (const float*)d_in[8];
    float* out = (float*)d_out;

    k_precompute<<<VOCAB / 128, 128>>>(emb_table, W_h, b_h);
    k_scan<<<BATCH, 128>>>(input_ids, W_h);
    k_logits<<<256, 256>>>(labels, W_out, b_out, out);
    k_loss<<<1, 256>>>(out + (out_size - 1), 256);
}

// round 2
// speedup vs baseline: 1.0168x; 1.0168x over previous
#include <cuda_runtime.h>
#include <math.h>

#define VOCAB 32000
#define EMB 128
#define HID 128
#define NLAB 9
#define BATCH 128
#define SEQ 1024
#define NTOK (BATCH * SEQ)

// Scratch (static device arrays: allocation-free, overwrite-only => graph-replay safe)
__device__ float g_T[VOCAB * HID];              // emb_table @ Wx + b_h   (16.4 MB, L2-resident)
__device__ float g_hidden[(size_t)NTOK * HID];  // hidden states (64 MB)
__device__ float g_partial[512];                // per-CTA loss partials

// ---- packed f32x2 helpers (Blackwell FFMA2: 2 fp32 FMAs per instruction) ----
__device__ __forceinline__ unsigned long long pack2(float lo, float hi) {
    unsigned long long r;
    asm("mov.b64 %0, {%1, %2};" : "=l"(r) : "f"(lo), "f"(hi));
    return r;
}
__device__ __forceinline__ unsigned long long fma2(unsigned long long a,
                                                   unsigned long long b,
                                                   unsigned long long c) {
    unsigned long long d;
    asm("fma.rn.f32x2 %0, %1, %2, %3;" : "=l"(d) : "l"(a), "l"(b), "l"(c));
    return d;
}
__device__ __forceinline__ float sum2(unsigned long long v) {
    float lo, hi;
    asm("mov.b64 {%0, %1}, %2;" : "=f"(lo), "=f"(hi) : "l"(v));
    return lo + hi;
}
__device__ __forceinline__ float tanh_fast(float x) {
    float r;
    asm("tanh.approx.f32 %0, %1;" : "=f"(r) : "f"(x));
    return r;
}

// ---------------------------------------------------------------------------
// Kernel 1: T[v][j] = sum_e emb[v][e] * Wx[e][j] + b_h[j]   (packed f32x2)
// ---------------------------------------------------------------------------
__global__ void __launch_bounds__(128) k_precompute(const float* __restrict__ emb,
                                                    const float* __restrict__ W_h,
                                                    const float* __restrict__ b_h) {
    const int j = threadIdx.x;
    unsigned long long wx2[EMB / 2];
#pragma unroll
    for (int e = 0; e < EMB / 2; e++)
        wx2[e] = pack2(W_h[(2 * e) * HID + j], W_h[(2 * e + 1) * HID + j]);
    const float bj = b_h[j];

    __shared__ __align__(16) float es[2][EMB];
    const int row0 = blockIdx.x * 128;

    es[0][j] = emb[(size_t)row0 * EMB + j];
    __syncthreads();

    for (int r = 0; r < 128; r++) {
        const int buf = r & 1;
        const int row = row0 + r;
        if (r + 1 < 128) es[buf ^ 1][j] = emb[(size_t)(row + 1) * EMB + j];

        const ulonglong2* e8 = (const ulonglong2*)es[buf];
        unsigned long long a0 = 0ull, a1 = 0ull, a2 = 0ull, a3 = 0ull;
#pragma unroll
        for (int k = 0; k < EMB / 4; k++) {
            ulonglong2 v = e8[k];
            if ((k & 1) == 0) { a0 = fma2(v.x, wx2[2 * k], a0); a1 = fma2(v.y, wx2[2 * k + 1], a1); }
            else              { a2 = fma2(v.x, wx2[2 * k], a2); a3 = fma2(v.y, wx2[2 * k + 1], a3); }
        }
        g_T[row * HID + j] = bj + (sum2(a0) + sum2(a1)) + (sum2(a2) + sum2(a3));
        __syncthreads();
    }
}

// ---------------------------------------------------------------------------
// Kernel 2: sequential scan. One CTA per batch row, thread j = hidden column j.
// Wh[:,j] packed-resident in registers; h double-buffered in SMEM; 2-deep xw
// prefetch from g_T; hw tanh; packed f32x2 FMAs (64/step instead of 128).
// ---------------------------------------------------------------------------
__global__ void __launch_bounds__(128) k_scan(const int* __restrict__ ids,
                                              const float* __restrict__ W_h) {
    const int b = blockIdx.x;
    const int j = threadIdx.x;

    unsigned long long wh2[HID / 2];
#pragma unroll
    for (int k = 0; k < HID / 2; k++)
        wh2[k] = pack2(W_h[(EMB + 2 * k) * HID + j], W_h[(EMB + 2 * k + 1) * HID + j]);

    __shared__ __align__(16) float hs[2][HID];
    __shared__ int ids_sh[SEQ];
    const int* idrow = ids + b * SEQ;
#pragma unroll
    for (int t = j; t < SEQ; t += 128) ids_sh[t] = idrow[t];
    hs[0][j] = 0.f;
    __syncthreads();

    float* hout = g_hidden + (size_t)b * SEQ * HID;

    // 2-deep prefetch pipeline: latency ~2 steps > L2-far (262cyc)
    float xw0 = g_T[ids_sh[0] * HID + j];
    float xw1 = g_T[ids_sh[1] * HID + j];

    for (int t = 0; t < SEQ; t++) {
        const int idn = ids_sh[(t + 2 < SEQ) ? (t + 2) : (SEQ - 1)];
        const float xw2 = g_T[idn * HID + j];  // lands at t+2

        const int buf = t & 1;
        const ulonglong2* h8 = (const ulonglong2*)hs[buf];
        unsigned long long a0 = 0ull, a1 = 0ull, a2 = 0ull, a3 = 0ull;
#pragma unroll
        for (int k = 0; k < HID / 4; k++) {
            ulonglong2 v = h8[k];
            if ((k & 1) == 0) { a0 = fma2(v.x, wh2[2 * k], a0); a1 = fma2(v.y, wh2[2 * k + 1], a1); }
            else              { a2 = fma2(v.x, wh2[2 * k], a2); a3 = fma2(v.y, wh2[2 * k + 1], a3); }
        }
        const float hv = tanh_fast(xw0 + (sum2(a0) + sum2(a1)) + (sum2(a2) + sum2(a3)));
        hs[buf ^ 1][j] = hv;
        hout[(size_t)t * HID + j] = hv;
        xw0 = xw1;
        xw1 = xw2;
        __syncthreads();
    }
}

// ---------------------------------------------------------------------------
// Kernel 3: logits + per-token NLL. One warp per token (strided).
// ---------------------------------------------------------------------------
__global__ void __launch_bounds__(256) k_logits(const int* __restrict__ labels,
                                                const float* __restrict__ W_out,
                                                const float* __restrict__ b_out,
                                                float* __restrict__ out_logits) {
    __shared__ float Wsh[HID * NLAB];
    __shared__ float bsh[NLAB];
    __shared__ float wsum[8];
    const int tid = threadIdx.x;
    for (int i = tid; i < HID * NLAB; i += blockDim.x) Wsh[i] = W_out[i];
    if (tid < NLAB) bsh[tid] = b_out[tid];
    __syncthreads();

    const int lane = tid & 31, warp = tid >> 5;
    const int gwarp = blockIdx.x * (blockDim.x >> 5) + warp;
    const int nwarp = gridDim.x * (blockDim.x >> 5);
    float lsum = 0.f;

    for (int tok = gwarp; tok < NTOK; tok += nwarp) {
        const float* h = g_hidden + (size_t)tok * HID;
        const float h0 = h[lane], h1 = h[lane + 32], h2 = h[lane + 64], h3 = h[lane + 96];
        float lg[NLAB];
#pragma unroll
        for (int l = 0; l < NLAB; l++) {
            float p = h0 * Wsh[lane * NLAB + l]
                    + h1 * Wsh[(lane + 32) * NLAB + l]
                    + h2 * Wsh[(lane + 64) * NLAB + l]
                    + h3 * Wsh[(lane + 96) * NLAB + l];
#pragma unroll
            for (int off = 16; off; off >>= 1) p += __shfl_xor_sync(0xffffffffu, p, off);
            lg[l] = p + bsh[l];
        }
        if (lane < NLAB) out_logits[(size_t)tok * NLAB + lane] = lg[lane];
        if (lane == 0) {
            float m = lg[0];
#pragma unroll
            for (int l = 1; l < NLAB; l++) m = fmaxf(m, lg[l]);
            float s = 0.f;
#pragma unroll
            for (int l = 0; l < NLAB; l++) s += expf(lg[l] - m);
            const float lse = m + logf(s);
            lsum += lse - lg[labels[tok]];
        }
    }
    if (lane == 0) wsum[warp] = lsum;
    __syncthreads();
    if (tid == 0) {
        float s = 0.f;
#pragma unroll
        for (int w = 0; w < 8; w++) s += wsum[w];
        g_partial[blockIdx.x] = s;  // overwrite, replay-safe
    }
}

// ---------------------------------------------------------------------------
// Kernel 4: reduce partials -> loss scalar
// ---------------------------------------------------------------------------
__global__ void __launch_bounds__(256) k_loss(float* __restrict__ out_loss, int nblocks) {
    __shared__ float s[256];
    float v = 0.f;
    for (int i = threadIdx.x; i < nblocks; i += 256) v += g_partial[i];
    s[threadIdx.x] = v;
    __syncthreads();
    for (int st = 128; st; st >>= 1) {
        if (threadIdx.x < st) s[threadIdx.x] += s[threadIdx.x + st];
        __syncthreads();
    }
    if (threadIdx.x == 0) out_loss[0] = s[0] / (float)NTOK;
}

extern "C" void kernel_launch(void* const* d_in, const int* in_sizes, int n_in,
                              void* d_out, int out_size) {
    const int*   input_ids = (const int*)d_in[0];
    const int*   labels    = (const int*)d_in[3];
    const float* emb_table = (const float*)d_in[4];
    const float* W_h       = (const float*)d_in[5];
    const float* b_h       = (const float*)d_in[6];
    const float* W_out     = (const float*)d_in[7];
    const float* b_out     = (const float*)d_in[8];
    float* out = (float*)d_out;

    k_precompute<<<VOCAB / 128, 128>>>(emb_table, W_h, b_h);
    k_scan<<<BATCH, 128>>>(input_ids, W_h);
    k_logits<<<256, 256>>>(labels, W_out, b_out, out);
    k_loss<<<1, 256>>>(out + (out_size - 1), 256);
}

// round 4
// speedup vs baseline: 1.1154x; 1.0970x over previous
#include <cuda_runtime.h>
#include <math.h>

#define VOCAB 32000
#define EMB 128
#define HID 128
#define NLAB 9
#define BATCH 128
#define SEQ 1024
#define NTOK (BATCH * SEQ)

// Scratch (static device arrays: allocation-free, overwrite-only => graph-replay safe)
__device__ float g_T[VOCAB * HID];              // emb_table @ Wx + b_h   (16.4 MB)
__device__ float g_hidden[(size_t)NTOK * HID];  // hidden states (64 MB, streaming)
__device__ float g_partial[512];                // per-CTA loss partials

// ---- packed f32x2 helpers (Blackwell FFMA2) ----
__device__ __forceinline__ unsigned long long pack2(float lo, float hi) {
    unsigned long long r;
    asm("mov.b64 %0, {%1, %2};" : "=l"(r) : "f"(lo), "f"(hi));
    return r;
}
__device__ __forceinline__ unsigned long long fma2(unsigned long long a,
                                                   unsigned long long b,
                                                   unsigned long long c) {
    unsigned long long d;
    asm("fma.rn.f32x2 %0, %1, %2, %3;" : "=l"(d) : "l"(a), "l"(b), "l"(c));
    return d;
}
__device__ __forceinline__ float sum2(unsigned long long v) {
    float lo, hi;
    asm("mov.b64 {%0, %1}, %2;" : "=f"(lo), "=f"(hi) : "l"(v));
    return lo + hi;
}
__device__ __forceinline__ float tanh_fast(float x) {
    float r;
    asm("tanh.approx.f32 %0, %1;" : "=f"(r) : "f"(x));
    return r;
}
// streaming evict-first store (g_hidden / logits)
__device__ __forceinline__ void stg_stream(float* p, float v) {
    asm volatile("st.global.cs.f32 [%0], %1;" :: "l"(p), "f"(v));
}

// ---------------------------------------------------------------------------
// Kernel 1: T[v][j] = sum_e emb[v][e] * Wx[e][j] + b_h[j]   (packed f32x2)
// ---------------------------------------------------------------------------
__global__ void __launch_bounds__(128) k_precompute(const float* __restrict__ emb,
                                                    const float* __restrict__ W_h,
                                                    const float* __restrict__ b_h) {
    const int j = threadIdx.x;
    unsigned long long wx2[EMB / 2];
#pragma unroll
    for (int e = 0; e < EMB / 2; e++)
        wx2[e] = pack2(W_h[(2 * e) * HID + j], W_h[(2 * e + 1) * HID + j]);
    const float bj = b_h[j];

    __shared__ __align__(16) float es[2][EMB];
    const int row0 = blockIdx.x * 128;

    es[0][j] = emb[(size_t)row0 * EMB + j];
    __syncthreads();

    for (int r = 0; r < 128; r++) {
        const int buf = r & 1;
        const int row = row0 + r;
        if (r + 1 < 128) es[buf ^ 1][j] = emb[(size_t)(row + 1) * EMB + j];

        const ulonglong2* e8 = (const ulonglong2*)es[buf];
        unsigned long long a0 = 0ull, a1 = 0ull, a2 = 0ull, a3 = 0ull;
#pragma unroll
        for (int k = 0; k < EMB / 4; k++) {
            ulonglong2 v = e8[k];
            if ((k & 1) == 0) { a0 = fma2(v.x, wx2[2 * k], a0); a1 = fma2(v.y, wx2[2 * k + 1], a1); }
            else              { a2 = fma2(v.x, wx2[2 * k], a2); a3 = fma2(v.y, wx2[2 * k + 1], a3); }
        }
        g_T[row * HID + j] = bj + (sum2(a0) + sum2(a1)) + (sum2(a2) + sum2(a3));
        __syncthreads();
    }
}

// ---------------------------------------------------------------------------
// Kernel 2: sequential scan. One CTA per batch row, thread j = hidden column j.
// Wh[:,j] packed in registers; h double-buffered in SMEM; 8-deep register ring
// prefetch of xw from g_T; streaming stores of hidden keep L2 for g_T.
// ---------------------------------------------------------------------------
__global__ void __launch_bounds__(128) k_scan(const int* __restrict__ ids,
                                              const float* __restrict__ W_h) {
    const int b = blockIdx.x;
    const int j = threadIdx.x;

    unsigned long long wh2[HID / 2];
#pragma unroll
    for (int k = 0; k < HID / 2; k++)
        wh2[k] = pack2(W_h[(EMB + 2 * k) * HID + j], W_h[(EMB + 2 * k + 1) * HID + j]);

    __shared__ __align__(16) float hs[2][HID];
    __shared__ int ids_sh[SEQ];
    const int* idrow = ids + b * SEQ;
#pragma unroll
    for (int t = j; t < SEQ; t += 128) ids_sh[t] = idrow[t];
    hs[0][j] = 0.f;
    __syncthreads();

    float* hout = g_hidden + (size_t)b * SEQ * HID;

    // 8-deep prefetch ring: coverage ~8 steps >> DRAM latency
    float xwb[8];
#pragma unroll
    for (int p = 0; p < 8; p++) xwb[p] = __ldg(g_T + ids_sh[p] * HID + j);

#pragma unroll 8
    for (int t = 0; t < SEQ; t++) {
        const float xw = xwb[t & 7];
        // issue next prefetch immediately so it overlaps the FMA chain
        const int tn = (t + 8 < SEQ) ? (t + 8) : (SEQ - 1);
        xwb[t & 7] = __ldg(g_T + ids_sh[tn] * HID + j);

        const int buf = t & 1;
        const ulonglong2* h8 = (const ulonglong2*)hs[buf];
        unsigned long long a0 = 0ull, a1 = 0ull, a2 = 0ull, a3 = 0ull;
#pragma unroll
        for (int k = 0; k < HID / 4; k++) {
            ulonglong2 v = h8[k];
            if ((k & 1) == 0) { a0 = fma2(v.x, wh2[2 * k], a0); a1 = fma2(v.y, wh2[2 * k + 1], a1); }
            else              { a2 = fma2(v.x, wh2[2 * k], a2); a3 = fma2(v.y, wh2[2 * k + 1], a3); }
        }
        const float hv = tanh_fast(xw + (sum2(a0) + sum2(a1)) + (sum2(a2) + sum2(a3)));
        hs[buf ^ 1][j] = hv;
        stg_stream(hout + (size_t)t * HID + j, hv);
        __syncthreads();
    }
}

// ---------------------------------------------------------------------------
// Kernel 3: logits + per-token NLL. One warp per token (strided).
// ---------------------------------------------------------------------------
__global__ void __launch_bounds__(256) k_logits(const int* __restrict__ labels,
                                                const float* __restrict__ W_out,
                                                const float* __restrict__ b_out,
                                                float* __restrict__ out_logits) {
    __shared__ float Wsh[HID * NLAB];
    __shared__ float bsh[NLAB];
    __shared__ float wsum[8];
    const int tid = threadIdx.x;
    for (int i = tid; i < HID * NLAB; i += blockDim.x) Wsh[i] = W_out[i];
    if (tid < NLAB) bsh[tid] = b_out[tid];
    __syncthreads();

    const int lane = tid & 31, warp = tid >> 5;
    const int gwarp = blockIdx.x * (blockDim.x >> 5) + warp;
    const int nwarp = gridDim.x * (blockDim.x >> 5);
    float lsum = 0.f;

    for (int tok = gwarp; tok < NTOK; tok += nwarp) {
        const float* h = g_hidden + (size_t)tok * HID;
        const float h0 = __ldcs(h + lane), h1 = __ldcs(h + lane + 32),
                    h2 = __ldcs(h + lane + 64), h3 = __ldcs(h + lane + 96);
        float lg[NLAB];
#pragma unroll
        for (int l = 0; l < NLAB; l++) {
            float p = h0 * Wsh[lane * NLAB + l]
                    + h1 * Wsh[(lane + 32) * NLAB + l]
                    + h2 * Wsh[(lane + 64) * NLAB + l]
                    + h3 * Wsh[(lane + 96) * NLAB + l];
#pragma unroll
            for (int off = 16; off; off >>= 1) p += __shfl_xor_sync(0xffffffffu, p, off);
            lg[l] = p + bsh[l];
        }
        if (lane < NLAB) stg_stream(out_logits + (size_t)tok * NLAB + lane, lg[lane]);
        if (lane == 0) {
            float m = lg[0];
#pragma unroll
            for (int l = 1; l < NLAB; l++) m = fmaxf(m, lg[l]);
            float s = 0.f;
#pragma unroll
            for (int l = 0; l < NLAB; l++) s += expf(lg[l] - m);
            const float lse = m + logf(s);
            lsum += lse - lg[labels[tok]];
        }
    }
    if (lane == 0) wsum[warp] = lsum;
    __syncthreads();
    if (tid == 0) {
        float s = 0.f;
#pragma unroll
        for (int w = 0; w < 8; w++) s += wsum[w];
        g_partial[blockIdx.x] = s;  // overwrite, replay-safe
    }
}

// ---------------------------------------------------------------------------
// Kernel 4: reduce partials -> loss scalar
// ---------------------------------------------------------------------------
__global__ void __launch_bounds__(256) k_loss(float* __restrict__ out_loss, int nblocks) {
    __shared__ float s[256];
    float v = 0.f;
    for (int i = threadIdx.x; i < nblocks; i += 256) v += g_partial[i];
    s[threadIdx.x] = v;
    __syncthreads();
    for (int st = 128; st; st >>= 1) {
        if (threadIdx.x < st) s[threadIdx.x] += s[threadIdx.x + st];
        __syncthreads();
    }
    if (threadIdx.x == 0) out_loss[0] = s[0] / (float)NTOK;
}

extern "C" void kernel_launch(void* const* d_in, const int* in_sizes, int n_in,
                              void* d_out, int out_size) {
    const int*   input_ids = (const int*)d_in[0];
    const int*   labels    = (const int*)d_in[3];
    const float* emb_table = (const float*)d_in[4];
    const float* W_h       = (const float*)d_in[5];
    const float* b_h       = (const float*)d_in[6];
    const float* W_out     = (const float*)d_in[7];
    const float* b_out     = (const float*)d_in[8];
    float* out = (float*)d_out;

    k_precompute<<<VOCAB / 128, 128>>>(emb_table, W_h, b_h);
    k_scan<<<BATCH, 128>>>(input_ids, W_h);
    k_logits<<<256, 256>>>(labels, W_out, b_out, out);
    k_loss<<<1, 256>>>(out + (out_size - 1), 256);
}